// round 2
// baseline (speedup 1.0000x reference)
#include <cuda_runtime.h>
#include <math.h>

#define N_NODES 50000
#define N_EDGES 800000
#define M_Y 256

// ---------------- scratch (device globals; no allocation) ----------------
__device__ float g_bufA[N_NODES * 128];
__device__ float g_bufB[N_NODES * 128];
__device__ float g_di[N_NODES];
__device__ int   g_cnt[N_NODES];
__device__ int   g_cur[N_NODES];
__device__ int   g_row[N_NODES + 1];
__device__ int   g_srcs[N_EDGES];
__device__ float g_enorm[N_EDGES];
__device__ int   g_bsums[64];
__device__ int   g_boffs[64];
__device__ float g_t[M_Y * 128];
__device__ int   g_is64;

// ---------------- edge_index dtype detection ----------------
// int64 little-endian values < 50000 have all-zero odd 32-bit words;
// int32 data has random node ids there. OR over 1024 odd words decides.
__global__ void k_detect(const unsigned int* __restrict__ w) {
    __shared__ unsigned int acc;
    if (threadIdx.x == 0) acc = 0u;
    __syncthreads();
    unsigned int v = 0u;
    for (int i = threadIdx.x; i < 1024; i += 256) v |= w[2 * i + 1];
    atomicOr(&acc, v);
    __syncthreads();
    if (threadIdx.x == 0) g_is64 = (acc == 0u) ? 1 : 0;
}

__device__ __forceinline__ int load_edge(const void* ei, long long idx) {
    if (g_is64) return (int)((const long long*)ei)[idx];
    return ((const int*)ei)[idx];
}

// ---------------- CSR build ----------------
__global__ void k_zero_csr() {
    int i = blockIdx.x * blockDim.x + threadIdx.x;
    if (i < N_NODES) { g_cnt[i] = 0; g_cur[i] = 0; }
}

__global__ void k_count(const void* __restrict__ ei, int E) {
    int e = blockIdx.x * blockDim.x + threadIdx.x;
    if (e >= E) return;
    int d = load_edge(ei, (long long)E + e);
    if ((unsigned)d < (unsigned)N_NODES) atomicAdd(&g_cnt[d], 1);
}

// pass 1: per-1024-chunk inclusive scan (Hillis-Steele)
__global__ void k_scan1() {
    __shared__ int sm[2][1024];
    int t = threadIdx.x;
    int gid = blockIdx.x * 1024 + t;
    int v = (gid < N_NODES) ? g_cnt[gid] : 0;
    int buf = 0;
    sm[0][t] = v;
    __syncthreads();
    for (int off = 1; off < 1024; off <<= 1) {
        int nv = sm[buf][t];
        if (t >= off) nv += sm[buf][t - off];
        sm[buf ^ 1][t] = nv;
        buf ^= 1;
        __syncthreads();
    }
    int inc = sm[buf][t];
    if (gid < N_NODES) g_row[gid + 1] = inc;
    if (t == 1023) g_bsums[blockIdx.x] = inc;
}

__global__ void k_scan2(int nb) {
    if (threadIdx.x == 0 && blockIdx.x == 0) {
        int acc = 0;
        for (int b = 0; b < nb; b++) { g_boffs[b] = acc; acc += g_bsums[b]; }
    }
}

__global__ void k_scan3() {
    int gid = blockIdx.x * 1024 + threadIdx.x;
    if (gid < N_NODES) {
        g_row[gid + 1] += g_boffs[blockIdx.x];
        g_di[gid] = rsqrtf((float)(g_cnt[gid] + 1));  // +1 self loop
    }
    if (gid == 0) g_row[0] = 0;
}

__global__ void k_scatter(const void* __restrict__ ei, int E) {
    int e = blockIdx.x * blockDim.x + threadIdx.x;
    if (e >= E) return;
    int s = load_edge(ei, e);
    int d = load_edge(ei, (long long)E + e);
    if ((unsigned)s >= (unsigned)N_NODES || (unsigned)d >= (unsigned)N_NODES) return;
    int pos = g_row[d] + atomicAdd(&g_cur[d], 1);
    g_srcs[pos] = s;
    g_enorm[pos] = g_di[s] * g_di[d];
}

// ---------------- GEMM: C[n,FO] = A[n,128] @ W[128,FO] ----------------
template <int FO>
__global__ void k_gemm(const float* __restrict__ A, const float* __restrict__ W,
                       float* __restrict__ C, int n) {
    extern __shared__ float smf[];
    float* Ws = smf;               // 128*FO
    float* As = smf + 128 * FO;    // 32*129
    int row0 = blockIdx.x * 32;
    for (int i = threadIdx.x; i < 128 * FO; i += 256) Ws[i] = W[i];
    for (int i = threadIdx.x; i < 32 * 128; i += 256) {
        int r = i >> 7, c = i & 127;
        int gr = row0 + r;
        As[r * 129 + c] = (gr < n) ? A[(size_t)gr * 128 + c] : 0.f;
    }
    __syncthreads();

    const int row = threadIdx.x & 31;
    const int c0 = (threadIdx.x >> 5) * (FO / 8);
    const int NV = FO / 32;  // float4s per thread (4 or 2)
    float acc[FO / 8];
#pragma unroll
    for (int k = 0; k < FO / 8; k++) acc[k] = 0.f;

    const float* arow = As + row * 129;
#pragma unroll 4
    for (int kk = 0; kk < 128; kk++) {
        float a = arow[kk];
        const float4* wv = (const float4*)(Ws + kk * FO + c0);
#pragma unroll
        for (int q = 0; q < NV; q++) {
            float4 w = wv[q];
            acc[q * 4 + 0] = fmaf(a, w.x, acc[q * 4 + 0]);
            acc[q * 4 + 1] = fmaf(a, w.y, acc[q * 4 + 1]);
            acc[q * 4 + 2] = fmaf(a, w.z, acc[q * 4 + 2]);
            acc[q * 4 + 3] = fmaf(a, w.w, acc[q * 4 + 3]);
        }
    }
    int gr = row0 + row;
    if (gr < n) {
        float4* cv = (float4*)(C + (size_t)gr * FO + c0);
#pragma unroll
        for (int q = 0; q < NV; q++)
            cv[q] = make_float4(acc[q * 4 + 0], acc[q * 4 + 1], acc[q * 4 + 2], acc[q * 4 + 3]);
    }
}

// ---------------- aggregation (one warp per node) ----------------
__global__ void k_agg128(const float* __restrict__ h, const float* __restrict__ bias,
                         float* __restrict__ out, int n) {
    int node = (blockIdx.x * blockDim.x + threadIdx.x) >> 5;
    int lane = threadIdx.x & 31;
    if (node >= n) return;
    const float4* hp = (const float4*)h;
    float di = g_di[node];
    float sn = di * di;
    float4 acc = hp[(size_t)node * 32 + lane];
    acc.x *= sn; acc.y *= sn; acc.z *= sn; acc.w *= sn;
    int beg = g_row[node], end = g_row[node + 1];
    for (int e = beg; e < end; e++) {
        int s = g_srcs[e];
        float wt = g_enorm[e];
        float4 v = hp[(size_t)s * 32 + lane];
        acc.x = fmaf(v.x, wt, acc.x);
        acc.y = fmaf(v.y, wt, acc.y);
        acc.z = fmaf(v.z, wt, acc.z);
        acc.w = fmaf(v.w, wt, acc.w);
    }
    float4 b = ((const float4*)bias)[lane];
    acc.x = fmaxf(acc.x + b.x, 0.f);
    acc.y = fmaxf(acc.y + b.y, 0.f);
    acc.z = fmaxf(acc.z + b.z, 0.f);
    acc.w = fmaxf(acc.w + b.w, 0.f);
    ((float4*)out)[(size_t)node * 32 + lane] = acc;
}

// layer 3: aggregate (F=64) + bias + row L2-normalize -> final x_emb.
__global__ void k_agg64n(const float* __restrict__ h, const float* __restrict__ bias,
                         float* __restrict__ out, int n) {
    int node = (blockIdx.x * blockDim.x + threadIdx.x) >> 5;
    int lane = threadIdx.x & 31;
    if (node >= n) return;
    const float2* hp = (const float2*)h;
    float di = g_di[node];
    float sn = di * di;
    float2 acc = hp[(size_t)node * 32 + lane];
    acc.x *= sn; acc.y *= sn;
    int beg = g_row[node], end = g_row[node + 1];
    for (int e = beg; e < end; e++) {
        int s = g_srcs[e];
        float wt = g_enorm[e];
        float2 v = hp[(size_t)s * 32 + lane];
        acc.x = fmaf(v.x, wt, acc.x);
        acc.y = fmaf(v.y, wt, acc.y);
    }
    float2 b = ((const float2*)bias)[lane];
    acc.x += b.x;
    acc.y += b.y;
    float ss = acc.x * acc.x + acc.y * acc.y;
#pragma unroll
    for (int o = 16; o; o >>= 1) ss += __shfl_xor_sync(0xffffffffu, ss, o);
    float inv = 1.f / fmaxf(sqrtf(ss), 1e-12f);
    ((float2*)out)[(size_t)node * 32 + lane] = make_float2(acc.x * inv, acc.y * inv);
}

// ---------------- y branch ----------------
__global__ void k_y1(const float* __restrict__ y, const float* __restrict__ gamma,
                     const float* __restrict__ beta, const float* __restrict__ Wm1,
                     const float* __restrict__ bm1) {
    __shared__ float red[256];
    int t = threadIdx.x;
    float v = y[t];
    red[t] = v;
    __syncthreads();
    for (int s = 128; s; s >>= 1) { if (t < s) red[t] += red[t + s]; __syncthreads(); }
    float mu = red[0] * (1.f / 256.f);
    __syncthreads();
    red[t] = v * v;
    __syncthreads();
    for (int s = 128; s; s >>= 1) { if (t < s) red[t] += red[t + s]; __syncthreads(); }
    float var = red[0] * (1.f / 256.f) - mu * mu;
    float yb = (v - mu) * rsqrtf(var + 1e-5f) * gamma[0] + beta[0];
    for (int j = 0; j < 128; j++)
        g_t[t * 128 + j] = fmaxf(fmaf(yb, Wm1[j], bm1[j]), 0.f);
}

__global__ void k_y2(const float* __restrict__ Wm2, const float* __restrict__ bm2,
                     float* __restrict__ out) {
    __shared__ float ts[128];
    __shared__ float wsum[2];
    int i = blockIdx.x, c = threadIdx.x;
    ts[c] = g_t[i * 128 + c];
    ts[c + 64] = g_t[i * 128 + c + 64];
    __syncthreads();
    float a = bm2[c];
#pragma unroll 4
    for (int j = 0; j < 128; j++) a = fmaf(ts[j], Wm2[j * 64 + c], a);
    float ss = a * a;
#pragma unroll
    for (int o = 16; o; o >>= 1) ss += __shfl_xor_sync(0xffffffffu, ss, o);
    if ((c & 31) == 0) wsum[c >> 5] = ss;
    __syncthreads();
    float inv = 1.f / fmaxf(sqrtf(wsum[0] + wsum[1]), 1e-12f);
    out[i * 64 + c] = a * inv;
}

// ---------------- launch ----------------
extern "C" void kernel_launch(void* const* d_in, const int* in_sizes, int n_in,
                              void* d_out, int out_size) {
    const float* x  = (const float*)d_in[0];
    const float* y  = (const float*)d_in[1];
    const void*  ei = d_in[2];
    const float* W1 = (const float*)d_in[3];  const float* b1  = (const float*)d_in[4];
    const float* W2 = (const float*)d_in[5];  const float* b2  = (const float*)d_in[6];
    const float* W3 = (const float*)d_in[7];  const float* b3  = (const float*)d_in[8];
    const float* bg = (const float*)d_in[9];  const float* bb  = (const float*)d_in[10];
    const float* Wm1 = (const float*)d_in[11]; const float* bm1 = (const float*)d_in[12];
    const float* Wm2 = (const float*)d_in[13]; const float* bm2 = (const float*)d_in[14];
    float* out = (float*)d_out;

    const int n = N_NODES;
    const int E = in_sizes[2] / 2;  // 800000 elements of either width

    const size_t sm128 = 128 * 128 * 4 + 32 * 129 * 4;
    const size_t sm64  = 128 * 64 * 4 + 32 * 129 * 4;
    cudaFuncSetAttribute(k_gemm<128>, cudaFuncAttributeMaxDynamicSharedMemorySize, (int)sm128);
    cudaFuncSetAttribute(k_gemm<64>,  cudaFuncAttributeMaxDynamicSharedMemorySize, (int)sm64);

    void *pA, *pB;
    cudaGetSymbolAddress(&pA, g_bufA);
    cudaGetSymbolAddress(&pB, g_bufB);
    float* bufA = (float*)pA;
    float* bufB = (float*)pB;

    // dtype probe + CSR build
    k_detect<<<1, 256>>>((const unsigned int*)ei);
    k_zero_csr<<<(n + 255) / 256, 256>>>();
    k_count<<<(E + 255) / 256, 256>>>(ei, E);
    const int NB = (n + 1023) / 1024;  // 49
    k_scan1<<<NB, 1024>>>();
    k_scan2<<<1, 32>>>(NB);
    k_scan3<<<NB, 1024>>>();
    k_scatter<<<(E + 255) / 256, 256>>>(ei, E);

    const int gb = (n + 31) / 32;
    const int aggBlocks = (n * 32 + 255) / 256;

    // layer 1
    k_gemm<128><<<gb, 256, sm128>>>(x, W1, bufA, n);
    k_agg128<<<aggBlocks, 256>>>(bufA, b1, bufB, n);
    // layer 2
    k_gemm<128><<<gb, 256, sm128>>>(bufB, W2, bufA, n);
    k_agg128<<<aggBlocks, 256>>>(bufA, b2, bufB, n);
    // layer 3 (+ normalize -> d_out)
    k_gemm<64><<<gb, 256, sm64>>>(bufB, W3, bufA, n);
    k_agg64n<<<aggBlocks, 256>>>(bufA, b3, out, n);

    // y branch
    k_y1<<<1, 256>>>(y, bg, bb, Wm1, bm1);
    k_y2<<<M_Y, 64>>>(Wm2, bm2, out + (size_t)N_NODES * 64);
}

// round 3
// speedup vs baseline: 1.1355x; 1.1355x over previous
#include <cuda_runtime.h>
#include <math.h>

#define N_NODES 50000
#define N_EDGES 800000
#define M_Y 256

// ---------------- scratch (device globals; no allocation) ----------------
__device__ float g_bufA[N_NODES * 128];
__device__ float g_bufB[N_NODES * 128];
__device__ float g_di[N_NODES];
__device__ int   g_cnt[N_NODES];
__device__ int   g_cur[N_NODES];
__device__ int   g_row[N_NODES + 1];
__device__ int2  g_epack[N_EDGES];   // .x = src, .y = __float_as_int(norm)
__device__ int   g_bsums[64];
__device__ int   g_boffs[64];
__device__ float g_t[M_Y * 128];
__device__ int   g_is64;

// ---------------- packed fp32x2 FMA (2x FFMA throughput on sm_103a) ----
__device__ __forceinline__ unsigned long long ffma2(unsigned long long a,
                                                    unsigned long long b,
                                                    unsigned long long c) {
    unsigned long long d;
    asm("fma.rn.f32x2 %0, %1, %2, %3;" : "=l"(d) : "l"(a), "l"(b), "l"(c));
    return d;
}
__device__ __forceinline__ unsigned long long pack2(float a) {
    unsigned long long r;
    asm("mov.b64 %0, {%1, %1};" : "=l"(r) : "f"(a));
    return r;
}

// ---------------- edge_index dtype detection ----------------
__global__ void k_detect(const unsigned int* __restrict__ w) {
    __shared__ unsigned int acc;
    if (threadIdx.x == 0) acc = 0u;
    __syncthreads();
    unsigned int v = 0u;
    for (int i = threadIdx.x; i < 1024; i += 256) v |= w[2 * i + 1];
    atomicOr(&acc, v);
    __syncthreads();
    if (threadIdx.x == 0) g_is64 = (acc == 0u) ? 1 : 0;
}

__device__ __forceinline__ int load_edge(const void* ei, long long idx) {
    if (g_is64) return (int)((const long long*)ei)[idx];
    return ((const int*)ei)[idx];
}

// ---------------- CSR build ----------------
__global__ void k_zero_csr() {
    int i = blockIdx.x * blockDim.x + threadIdx.x;
    if (i < N_NODES) { g_cnt[i] = 0; g_cur[i] = 0; }
}

__global__ void k_count(const void* __restrict__ ei, int E) {
    int e = blockIdx.x * blockDim.x + threadIdx.x;
    if (e >= E) return;
    int d = load_edge(ei, (long long)E + e);
    if ((unsigned)d < (unsigned)N_NODES) atomicAdd(&g_cnt[d], 1);
}

__global__ void k_scan1() {
    __shared__ int sm[2][1024];
    int t = threadIdx.x;
    int gid = blockIdx.x * 1024 + t;
    int v = (gid < N_NODES) ? g_cnt[gid] : 0;
    int buf = 0;
    sm[0][t] = v;
    __syncthreads();
    for (int off = 1; off < 1024; off <<= 1) {
        int nv = sm[buf][t];
        if (t >= off) nv += sm[buf][t - off];
        sm[buf ^ 1][t] = nv;
        buf ^= 1;
        __syncthreads();
    }
    int inc = sm[buf][t];
    if (gid < N_NODES) g_row[gid + 1] = inc;
    if (t == 1023) g_bsums[blockIdx.x] = inc;
}

__global__ void k_scan2(int nb) {
    if (threadIdx.x == 0 && blockIdx.x == 0) {
        int acc = 0;
        for (int b = 0; b < nb; b++) { g_boffs[b] = acc; acc += g_bsums[b]; }
    }
}

__global__ void k_scan3() {
    int gid = blockIdx.x * 1024 + threadIdx.x;
    if (gid < N_NODES) {
        g_row[gid + 1] += g_boffs[blockIdx.x];
        g_di[gid] = rsqrtf((float)(g_cnt[gid] + 1));  // +1 self loop
    }
    if (gid == 0) g_row[0] = 0;
}

__global__ void k_scatter(const void* __restrict__ ei, int E) {
    int e = blockIdx.x * blockDim.x + threadIdx.x;
    if (e >= E) return;
    int s = load_edge(ei, e);
    int d = load_edge(ei, (long long)E + e);
    if ((unsigned)s >= (unsigned)N_NODES || (unsigned)d >= (unsigned)N_NODES) return;
    int pos = g_row[d] + atomicAdd(&g_cur[d], 1);
    g_epack[pos] = make_int2(s, __float_as_int(g_di[s] * g_di[d]));
}

// ---------------- GEMM: C[n,FO] = A[n,128] @ W[128,FO] ----------------
// 32 rows/block, 256 threads, W resident in smem, A staged at stride 132
// (16B aligned + LDS.128 conflict-free). Inner product via fma.rn.f32x2.
template <int FO>
__global__ void k_gemm(const float* __restrict__ A, const float* __restrict__ W,
                       float* __restrict__ C, int n) {
    extern __shared__ float smf[];
    float* Ws = smf;               // 128*FO
    float* As = smf + 128 * FO;    // 32*132
    int row0 = blockIdx.x * 32;
    for (int i = threadIdx.x; i < 128 * FO / 4; i += 256)
        ((float4*)Ws)[i] = ((const float4*)W)[i];
    for (int i = threadIdx.x; i < 32 * 32; i += 256) {
        int r = i >> 5, c = i & 31;
        int gr = row0 + r;
        float4 v = (gr < n) ? ((const float4*)A)[(size_t)gr * 32 + c]
                            : make_float4(0.f, 0.f, 0.f, 0.f);
        *(float4*)(As + r * 132 + c * 4) = v;
    }
    __syncthreads();

    const int row = threadIdx.x & 31;
    const int c0 = (threadIdx.x >> 5) * (FO / 8);
    constexpr int NP = FO / 16;  // packed f32x2 accumulators per thread
    unsigned long long acc[NP];
#pragma unroll
    for (int q = 0; q < NP; q++) acc[q] = 0ull;

    const float* arow = As + row * 132;
#pragma unroll 2
    for (int k4 = 0; k4 < 128; k4 += 4) {
        float4 av = *(const float4*)(arow + k4);
        float as[4] = {av.x, av.y, av.z, av.w};
#pragma unroll
        for (int j = 0; j < 4; j++) {
            unsigned long long a2 = pack2(as[j]);
            const ulonglong2* wv = (const ulonglong2*)(Ws + (k4 + j) * FO + c0);
#pragma unroll
            for (int q = 0; q < NP / 2; q++) {
                ulonglong2 w = wv[q];
                acc[2 * q]     = ffma2(a2, w.x, acc[2 * q]);
                acc[2 * q + 1] = ffma2(a2, w.y, acc[2 * q + 1]);
            }
        }
    }
    int gr = row0 + row;
    if (gr < n) {
        float4* cv = (float4*)(C + (size_t)gr * FO + c0);
#pragma unroll
        for (int q = 0; q < NP / 2; q++) {
            union { unsigned long long u; float2 f; } u0, u1;
            u0.u = acc[2 * q]; u1.u = acc[2 * q + 1];
            cv[q] = make_float4(u0.f.x, u0.f.y, u1.f.x, u1.f.y);
        }
    }
}

// ---------------- aggregation (one warp per node) ----------------
__global__ void k_agg128(const float* __restrict__ h, const float* __restrict__ bias,
                         float* __restrict__ out, int n) {
    int node = (blockIdx.x * blockDim.x + threadIdx.x) >> 5;
    int lane = threadIdx.x & 31;
    if (node >= n) return;
    const float4* hp = (const float4*)h;
    float di = g_di[node];
    float sn = di * di;
    float4 acc = hp[(size_t)node * 32 + lane];
    acc.x *= sn; acc.y *= sn; acc.z *= sn; acc.w *= sn;
    int e = g_row[node], end = g_row[node + 1];
    for (; e + 1 < end; e += 2) {
        int2 p0 = g_epack[e];
        int2 p1 = g_epack[e + 1];
        float4 v0 = hp[(size_t)p0.x * 32 + lane];
        float4 v1 = hp[(size_t)p1.x * 32 + lane];
        float w0 = __int_as_float(p0.y), w1 = __int_as_float(p1.y);
        acc.x = fmaf(v0.x, w0, acc.x); acc.y = fmaf(v0.y, w0, acc.y);
        acc.z = fmaf(v0.z, w0, acc.z); acc.w = fmaf(v0.w, w0, acc.w);
        acc.x = fmaf(v1.x, w1, acc.x); acc.y = fmaf(v1.y, w1, acc.y);
        acc.z = fmaf(v1.z, w1, acc.z); acc.w = fmaf(v1.w, w1, acc.w);
    }
    if (e < end) {
        int2 p = g_epack[e];
        float4 v = hp[(size_t)p.x * 32 + lane];
        float wt = __int_as_float(p.y);
        acc.x = fmaf(v.x, wt, acc.x); acc.y = fmaf(v.y, wt, acc.y);
        acc.z = fmaf(v.z, wt, acc.z); acc.w = fmaf(v.w, wt, acc.w);
    }
    float4 b = ((const float4*)bias)[lane];
    acc.x = fmaxf(acc.x + b.x, 0.f);
    acc.y = fmaxf(acc.y + b.y, 0.f);
    acc.z = fmaxf(acc.z + b.z, 0.f);
    acc.w = fmaxf(acc.w + b.w, 0.f);
    ((float4*)out)[(size_t)node * 32 + lane] = acc;
}

// layer 3: aggregate (F=64) + bias + row L2-normalize -> final x_emb.
__global__ void k_agg64n(const float* __restrict__ h, const float* __restrict__ bias,
                         float* __restrict__ out, int n) {
    int node = (blockIdx.x * blockDim.x + threadIdx.x) >> 5;
    int lane = threadIdx.x & 31;
    if (node >= n) return;
    const float2* hp = (const float2*)h;
    float di = g_di[node];
    float sn = di * di;
    float2 acc = hp[(size_t)node * 32 + lane];
    acc.x *= sn; acc.y *= sn;
    int e = g_row[node], end = g_row[node + 1];
    for (; e + 1 < end; e += 2) {
        int2 p0 = g_epack[e];
        int2 p1 = g_epack[e + 1];
        float2 v0 = hp[(size_t)p0.x * 32 + lane];
        float2 v1 = hp[(size_t)p1.x * 32 + lane];
        float w0 = __int_as_float(p0.y), w1 = __int_as_float(p1.y);
        acc.x = fmaf(v0.x, w0, acc.x); acc.y = fmaf(v0.y, w0, acc.y);
        acc.x = fmaf(v1.x, w1, acc.x); acc.y = fmaf(v1.y, w1, acc.y);
    }
    if (e < end) {
        int2 p = g_epack[e];
        float2 v = hp[(size_t)p.x * 32 + lane];
        float wt = __int_as_float(p.y);
        acc.x = fmaf(v.x, wt, acc.x); acc.y = fmaf(v.y, wt, acc.y);
    }
    float2 b = ((const float2*)bias)[lane];
    acc.x += b.x;
    acc.y += b.y;
    float ss = acc.x * acc.x + acc.y * acc.y;
#pragma unroll
    for (int o = 16; o; o >>= 1) ss += __shfl_xor_sync(0xffffffffu, ss, o);
    float inv = 1.f / fmaxf(sqrtf(ss), 1e-12f);
    ((float2*)out)[(size_t)node * 32 + lane] = make_float2(acc.x * inv, acc.y * inv);
}

// ---------------- y branch ----------------
__global__ void k_y1(const float* __restrict__ y, const float* __restrict__ gamma,
                     const float* __restrict__ beta, const float* __restrict__ Wm1,
                     const float* __restrict__ bm1) {
    __shared__ float red[256];
    int t = threadIdx.x;
    float v = y[t];
    red[t] = v;
    __syncthreads();
    for (int s = 128; s; s >>= 1) { if (t < s) red[t] += red[t + s]; __syncthreads(); }
    float mu = red[0] * (1.f / 256.f);
    __syncthreads();
    red[t] = v * v;
    __syncthreads();
    for (int s = 128; s; s >>= 1) { if (t < s) red[t] += red[t + s]; __syncthreads(); }
    float var = red[0] * (1.f / 256.f) - mu * mu;
    float yb = (v - mu) * rsqrtf(var + 1e-5f) * gamma[0] + beta[0];
    for (int j = 0; j < 128; j++)
        g_t[t * 128 + j] = fmaxf(fmaf(yb, Wm1[j], bm1[j]), 0.f);
}

__global__ void k_y2(const float* __restrict__ Wm2, const float* __restrict__ bm2,
                     float* __restrict__ out) {
    __shared__ float ts[128];
    __shared__ float wsum[2];
    int i = blockIdx.x, c = threadIdx.x;
    ts[c] = g_t[i * 128 + c];
    ts[c + 64] = g_t[i * 128 + c + 64];
    __syncthreads();
    float a = bm2[c];
#pragma unroll 4
    for (int j = 0; j < 128; j++) a = fmaf(ts[j], Wm2[j * 64 + c], a);
    float ss = a * a;
#pragma unroll
    for (int o = 16; o; o >>= 1) ss += __shfl_xor_sync(0xffffffffu, ss, o);
    if ((c & 31) == 0) wsum[c >> 5] = ss;
    __syncthreads();
    float inv = 1.f / fmaxf(sqrtf(wsum[0] + wsum[1]), 1e-12f);
    out[i * 64 + c] = a * inv;
}

// ---------------- launch ----------------
extern "C" void kernel_launch(void* const* d_in, const int* in_sizes, int n_in,
                              void* d_out, int out_size) {
    const float* x  = (const float*)d_in[0];
    const float* y  = (const float*)d_in[1];
    const void*  ei = d_in[2];
    const float* W1 = (const float*)d_in[3];  const float* b1  = (const float*)d_in[4];
    const float* W2 = (const float*)d_in[5];  const float* b2  = (const float*)d_in[6];
    const float* W3 = (const float*)d_in[7];  const float* b3  = (const float*)d_in[8];
    const float* bg = (const float*)d_in[9];  const float* bb  = (const float*)d_in[10];
    const float* Wm1 = (const float*)d_in[11]; const float* bm1 = (const float*)d_in[12];
    const float* Wm2 = (const float*)d_in[13]; const float* bm2 = (const float*)d_in[14];
    float* out = (float*)d_out;

    const int n = N_NODES;
    const int E = in_sizes[2] / 2;

    const size_t sm128 = 128 * 128 * 4 + 32 * 132 * 4;
    const size_t sm64  = 128 * 64 * 4 + 32 * 132 * 4;
    cudaFuncSetAttribute(k_gemm<128>, cudaFuncAttributeMaxDynamicSharedMemorySize, (int)sm128);
    cudaFuncSetAttribute(k_gemm<64>,  cudaFuncAttributeMaxDynamicSharedMemorySize, (int)sm64);

    void *pA, *pB;
    cudaGetSymbolAddress(&pA, g_bufA);
    cudaGetSymbolAddress(&pB, g_bufB);
    float* bufA = (float*)pA;
    float* bufB = (float*)pB;

    // dtype probe + CSR build
    k_detect<<<1, 256>>>((const unsigned int*)ei);
    k_zero_csr<<<(n + 255) / 256, 256>>>();
    k_count<<<(E + 255) / 256, 256>>>(ei, E);
    const int NB = (n + 1023) / 1024;  // 49
    k_scan1<<<NB, 1024>>>();
    k_scan2<<<1, 32>>>(NB);
    k_scan3<<<NB, 1024>>>();
    k_scatter<<<(E + 255) / 256, 256>>>(ei, E);

    const int gb = (n + 31) / 32;
    const int aggBlocks = (n * 32 + 255) / 256;

    // layer 1
    k_gemm<128><<<gb, 256, sm128>>>(x, W1, bufA, n);
    k_agg128<<<aggBlocks, 256>>>(bufA, b1, bufB, n);
    // layer 2
    k_gemm<128><<<gb, 256, sm128>>>(bufB, W2, bufA, n);
    k_agg128<<<aggBlocks, 256>>>(bufA, b2, bufB, n);
    // layer 3 (+ normalize -> d_out)
    k_gemm<64><<<gb, 256, sm64>>>(bufB, W3, bufA, n);
    k_agg64n<<<aggBlocks, 256>>>(bufA, b3, out, n);

    // y branch
    k_y1<<<1, 256>>>(y, bg, bb, Wm1, bm1);
    k_y2<<<M_Y, 64>>>(Wm2, bm2, out + (size_t)N_NODES * 64);
}